// round 10
// baseline (speedup 1.0000x reference)
#include <cuda_runtime.h>
#include <cuda_bf16.h>

#define JAX_PARTITIONABLE 1

// ---------------- scratch (__device__ globals; no allocation) ----------------
__device__ float g_T[8192 * 128];          // X_in @ theta
__device__ float g_U[8192 * 128];          // xi @ w_trans0
__device__ float g_U1[8192 * 128];         // xi @ w_trans1
__device__ float g_X[8192 * 128];          // X1 then X2
__device__ float g_msg[4096 * 128];        // edge messages (ew-scaled)
__device__ float g_msgP[8 * 4096 * 128];   // split-K partials for Hs GEMM
__device__ float g_ZP[4 * 8192 * 128];     // split-K partials for Ht^T GEMM

// ------------------------------- helpers ------------------------------------
__device__ __forceinline__ unsigned rotl32(unsigned v, int s) {
    return __funnelshift_l(v, v, s);
}
__device__ __forceinline__ unsigned smem_u32(const void* p) {
    unsigned a;
    asm("{ .reg .u64 t; cvta.to.shared.u64 t, %1; cvt.u32.u64 %0, t; }"
        : "=r"(a) : "l"(p));
    return a;
}

// bf16 2-way split of a k-pair (f0 = even k, f1 = odd k) -> packed hi, lo u32.
__device__ __forceinline__ void split_pair(float f0, float f1,
                                           unsigned& H, unsigned& L) {
    __nv_bfloat162 h = __floats2bfloat162_rn(f0, f1);
    float r0 = f0 - __bfloat162float(h.x);
    float r1 = f1 - __bfloat162float(h.y);
    __nv_bfloat162 l = __floats2bfloat162_rn(r0, r1);
    H = *reinterpret_cast<unsigned*>(&h);
    L = *reinterpret_cast<unsigned*>(&l);
}

// m16n8k16 bf16 mma, fp32 accumulate
__device__ __forceinline__ void mma16(float c[4], const unsigned a[4], const unsigned b[2]) {
    asm("mma.sync.aligned.m16n8k16.row.col.f32.bf16.bf16.f32 "
        "{%0,%1,%2,%3},{%4,%5,%6,%7},{%8,%9},{%0,%1,%2,%3};"
        : "+f"(c[0]), "+f"(c[1]), "+f"(c[2]), "+f"(c[3])
        : "r"(a[0]), "r"(a[1]), "r"(a[2]), "r"(a[3]), "r"(b[0]), "r"(b[1]));
}

// ldmatrix: 4x (8x8 b16) tiles; per-lane row addresses
__device__ __forceinline__ void ldm_x4(unsigned r[4], unsigned addr) {
    asm("ldmatrix.sync.aligned.m8n8.x4.shared.b16 {%0,%1,%2,%3}, [%4];"
        : "=r"(r[0]), "=r"(r[1]), "=r"(r[2]), "=r"(r[3]) : "r"(addr));
}

// JAX threefry2x32, key = (0, 42). Random bits for flat element j of (8192,128).
__device__ __forceinline__ unsigned jax_dropout_bits(unsigned j) {
    const unsigned k0 = 0u, k1 = 42u;
    const unsigned ks2 = k0 ^ k1 ^ 0x1BD11BDAu;
    unsigned x0, x1;
#if JAX_PARTITIONABLE
    x0 = 0u + k0;
    x1 = j + k1;
#else
    const unsigned HALF = 524288u;
    unsigned i = (j < HALF) ? j : (j - HALF);
    x0 = i + k0;
    x1 = (i + HALF) + k1;
#endif
#define TFR(r) do { x0 += x1; x1 = rotl32(x1, (r)); x1 ^= x0; } while (0)
    TFR(13); TFR(15); TFR(26); TFR(6);   x0 += k1;  x1 += ks2 + 1u;
    TFR(17); TFR(29); TFR(16); TFR(24);  x0 += ks2; x1 += k0 + 2u;
    TFR(13); TFR(15); TFR(26); TFR(6);   x0 += k0;  x1 += k1 + 3u;
    TFR(17); TFR(29); TFR(16); TFR(24);  x0 += k1;  x1 += ks2 + 4u;
    TFR(13); TFR(15); TFR(26); TFR(6);   x0 += ks2; x1 += k0 + 5u;
#undef TFR
#if JAX_PARTITIONABLE
    return x0 ^ x1;
#else
    return (j < 524288u) ? x0 : x1;
#endif
}

// ====================== 3-term bf16-split GEMM (ldmatrix) ====================
// C[M,128] = op(A) @ B;  B is [K,128] row-major fp32.
// Both operands staged as [row 128][k-pair 16 + 4 pad] u32 tiles (hi & lo),
// B stored n-major so BOTH fragments come from conflict-free ldmatrix.x4.
// 512 threads = 16 warps (4M x 4N), warp tile 32x32, k32/iter, double-buffered.
static const int TSZ = 2560;             // one tile (128 rows x 20 u32)
static const int BUFS = 4 * TSZ;         // AH AL BH BL
static const int SM_BYTES = 2 * BUFS * 4; // 81920 B

// MODE 0: G[row][k] row-major (k contiguous) -> vectorized loads
// MODE 1: G[k][row] (row contiguous)         -> lane-coalesced strided loads
template <int MODE>
__device__ __forceinline__ void load_op(const float* __restrict__ G, int ld,
                                        int base, int kc, int idx, int c,
                                        float v[8]) {
    if (MODE == 0) {
        const float4* p = (const float4*)(G + (size_t)(base + idx) * ld + kc + c * 8);
        float4 a = p[0], b = p[1];
        v[0] = a.x; v[1] = a.y; v[2] = a.z; v[3] = a.w;
        v[4] = b.x; v[5] = b.y; v[6] = b.z; v[7] = b.w;
    } else {
        const float* p = G + (size_t)(kc + c * 8) * ld + base + idx;
#pragma unroll
        for (int j = 0; j < 8; ++j) v[j] = p[(size_t)j * ld];
    }
}

__device__ __forceinline__ void store_tile(unsigned* __restrict__ tH,
                                           unsigned* __restrict__ tL,
                                           int idx, int c, const float v[8]) {
    uint4 H, L;
    split_pair(v[0], v[1], H.x, L.x);
    split_pair(v[2], v[3], H.y, L.y);
    split_pair(v[4], v[5], H.z, L.z);
    split_pair(v[6], v[7], H.w, L.w);
    *(uint4*)&tH[idx * 20 + c * 4] = H;
    *(uint4*)&tL[idx * 20 + c * 4] = L;
}

template <bool TRANS_A>
__device__ __forceinline__ void gemm_body_bf(
    const float* __restrict__ A, const float* __restrict__ B,
    float* __restrict__ Cp, int lda, int k_iters, int mblk, int split, int gx)
{
    extern __shared__ unsigned sm[];
    const unsigned sbase = smem_u32(sm);
    const int tid = threadIdx.x;
    const int lane = tid & 31;
    const int wid = tid >> 5;              // 0..15
    const int wm = (wid & 3) * 32;
    const int wn = (wid >> 2) * 32;
    const int g = lane >> 2;               // 0..7
    const int t = lane & 3;                // 0..3
    const int m0 = mblk * 128;
    const int k00 = split * k_iters * 32;

    // staging task: idx = row/col (0..127), sc = 16B chunk (0..3)
    const int sidx = tid & 127;
    const int sc = tid >> 7;

    // ldmatrix lane geometry: sub-matrix = lane/8
    const int sub = lane >> 3, lr = lane & 7;
    const int frow = (sub & 1) * 8 + lr;   // row offset within 16-row block
    const int fco = sub >> 1;              // chunk offset 0/1

    float acc[2][4][4];
#pragma unroll
    for (int mt = 0; mt < 2; ++mt)
#pragma unroll
        for (int nt = 0; nt < 4; ++nt)
#pragma unroll
            for (int i = 0; i < 4; ++i) acc[mt][nt][i] = 0.f;

    const int AMODE = TRANS_A ? 1 : 0;
    float va[8], vb[8];

    // prologue: tile 0 -> buffer 0
    int kc = k00;
    load_op<AMODE>(A, lda, m0, kc, sidx, sc, va);
    load_op<1>(B, 128, 0, kc, sidx, sc, vb);
    store_tile(sm, sm + TSZ, sidx, sc, va);
    store_tile(sm + 2 * TSZ, sm + 3 * TSZ, sidx, sc, vb);
    __syncthreads();

    for (int it = 0; it < k_iters; ++it) {
        const unsigned bufo = (unsigned)(it & 1) * BUFS;   // u32 offset
        const bool hn = (it + 1 < k_iters);

        if (hn) {  // next-tile global loads issued early, hidden under mmas
            kc = k00 + (it + 1) * 32;
            load_op<AMODE>(A, lda, m0, kc, sidx, sc, va);
            load_op<1>(B, 128, 0, kc, sidx, sc, vb);
        }

#pragma unroll
        for (int ks = 0; ks < 2; ++ks) {
            const unsigned chunk = (unsigned)(ks * 2 + fco);
            unsigned aH[2][4], aL[2][4], bH[2][4], bL[2][4];
#pragma unroll
            for (int mt = 0; mt < 2; ++mt) {
                unsigned ao = bufo + (unsigned)((wm + mt * 16 + frow) * 20) + chunk * 4;
                ldm_x4(aH[mt], sbase + ao * 4);
                ldm_x4(aL[mt], sbase + (ao + TSZ) * 4);
            }
#pragma unroll
            for (int p = 0; p < 2; ++p) {
                unsigned bo = bufo + 2 * TSZ
                            + (unsigned)((wn + p * 16 + frow) * 20) + chunk * 4;
                ldm_x4(bH[p], sbase + bo * 4);
                ldm_x4(bL[p], sbase + (bo + TSZ) * 4);
            }
#pragma unroll
            for (int nt = 0; nt < 4; ++nt) {
                const int p = nt >> 1, o = nt & 1;
                unsigned bh[2] = { bH[p][o], bH[p][2 + o] };
                unsigned bl[2] = { bL[p][o], bL[p][2 + o] };
#pragma unroll
                for (int mt = 0; mt < 2; ++mt) {
                    mma16(acc[mt][nt], aH[mt], bh);   // hi*hi
                    mma16(acc[mt][nt], aL[mt], bh);   // lo*hi
                    mma16(acc[mt][nt], aH[mt], bl);   // hi*lo
                }
            }
        }

        if (hn) {  // stage next tile into the other buffer
            unsigned* nb = sm + ((it + 1) & 1) * BUFS;
            store_tile(nb, nb + TSZ, sidx, sc, va);
            store_tile(nb + 2 * TSZ, nb + 3 * TSZ, sidx, sc, vb);
        }
        __syncthreads();
    }

    float* Cb = Cp + (size_t)split * gx * (128 * 128) + (size_t)m0 * 128;
#pragma unroll
    for (int mt = 0; mt < 2; ++mt)
#pragma unroll
        for (int nt = 0; nt < 4; ++nt) {
            const int r = wm + mt * 16 + g;
            const int c = wn + nt * 8 + t * 2;
            *(float2*)&Cb[(size_t)r * 128 + c] =
                make_float2(acc[mt][nt][0], acc[mt][nt][1]);
            *(float2*)&Cb[(size_t)(r + 8) * 128 + c] =
                make_float2(acc[mt][nt][2], acc[mt][nt][3]);
        }
}

// ------------------------------ GEMM kernels ---------------------------------
template <bool TRANS_A>
__global__ __launch_bounds__(512, 1)
void gemm_big(const float* __restrict__ A, const float* __restrict__ B,
              float* __restrict__ Cp, int lda, int k_iters)
{
    gemm_body_bf<TRANS_A>(A, B, Cp, lda, k_iters, blockIdx.x, blockIdx.y, gridDim.x);
}

struct GemmJob { const float* A; const float* B; float* C; };

__global__ __launch_bounds__(512, 1)
void gemm_small3(GemmJob j0, GemmJob j1, GemmJob j2)
{
    GemmJob j = (blockIdx.z == 0) ? j0 : ((blockIdx.z == 1) ? j1 : j2);
    gemm_body_bf<false>(j.A, j.B, j.C, 128, 4, blockIdx.x, 0, 64);
}

__global__ __launch_bounds__(512, 1)
void gemm_small1(const float* __restrict__ A, const float* __restrict__ B,
                 float* __restrict__ C)
{
    gemm_body_bf<false>(A, B, C, 128, 4, blockIdx.x, 0, 64);
}

// ------------------------ reduce / epilogue kernels --------------------------
__global__ void reduce_msg_k(const float* __restrict__ P, const float* __restrict__ ew,
                             float* __restrict__ out)
{
    const int i = blockIdx.x * 256 + threadIdx.x;
    float s = 0.f;
#pragma unroll
    for (int j = 0; j < 8; ++j) s += P[(size_t)j * (4096 * 128) + i];
    out[i] = s * ew[i >> 7];
}

__global__ void reduce_x1_k(const float* __restrict__ P, const float* __restrict__ U,
                            const float* __restrict__ bias, float* __restrict__ X1)
{
    const int i = blockIdx.x * 256 + threadIdx.x;
    float s = U[i] + bias[i & 127];
#pragma unroll
    for (int j = 0; j < 4; ++j) s += P[(size_t)j * (8192 * 128) + i];
    s = (s >= 0.f) ? s : 0.01f * s;
    const unsigned bits = jax_dropout_bits((unsigned)i);
    X1[i] = (bits & 0x80000000u) ? 0.f : (s + s);
}

__global__ void reduce_x2_k(const float* __restrict__ P, const float* __restrict__ U,
                            const float* __restrict__ bias, float* __restrict__ X2)
{
    const int i = blockIdx.x * 256 + threadIdx.x;
    float s = U[i] + bias[i & 127];
#pragma unroll
    for (int j = 0; j < 4; ++j) s += P[(size_t)j * (8192 * 128) + i];
    s = (s >= 0.f) ? s : 0.01f * s;
    s = (s >= 0.f) ? s : 0.01f * s;
    X2[i] = s;
}

__global__ void fc_k(const float* __restrict__ X, const float* __restrict__ state,
                     const float* __restrict__ fcw, const float* __restrict__ fcb,
                     float* __restrict__ out)
{
    const int n = blockIdx.x * 256 + threadIdx.x;
    const float4* xr = (const float4*)(X + (size_t)n * 128);
    const float4* w4 = (const float4*)fcw;
    float s = 0.f;
#pragma unroll
    for (int i = 0; i < 32; ++i) {
        float4 a = xr[i], b = w4[i];
        s += a.x * b.x + a.y * b.y + a.z * b.z + a.w * b.w;
    }
    out[n] = s + state[n] * fcw[128] + fcb[0];
}

// --------------------------------- launch ------------------------------------
extern "C" void kernel_launch(void* const* d_in, const int* in_sizes, int n_in,
                              void* d_out, int out_size)
{
    const float* xi   = (const float*)d_in[0];
    const float* x    = (const float*)d_in[1];
    const float* Ht   = (const float*)d_in[2];
    const float* Hs   = (const float*)d_in[3];
    const float* st   = (const float*)d_in[4];
    const float* w0   = (const float*)d_in[5];
    const float* th0  = (const float*)d_in[6];
    const float* ew0  = (const float*)d_in[7];
    const float* b0   = (const float*)d_in[8];
    const float* w1   = (const float*)d_in[9];
    const float* th1  = (const float*)d_in[10];
    const float* ew1  = (const float*)d_in[11];
    const float* b1   = (const float*)d_in[12];
    const float* fcw  = (const float*)d_in[13];
    const float* fcb  = (const float*)d_in[14];
    float* out = (float*)d_out;

    float *T, *U, *U1, *X, *M, *MP, *ZP;
    cudaGetSymbolAddress((void**)&T,  g_T);
    cudaGetSymbolAddress((void**)&U,  g_U);
    cudaGetSymbolAddress((void**)&U1, g_U1);
    cudaGetSymbolAddress((void**)&X,  g_X);
    cudaGetSymbolAddress((void**)&M,  g_msg);
    cudaGetSymbolAddress((void**)&MP, g_msgP);
    cudaGetSymbolAddress((void**)&ZP, g_ZP);

    cudaFuncSetAttribute(gemm_big<false>, cudaFuncAttributeMaxDynamicSharedMemorySize, SM_BYTES);
    cudaFuncSetAttribute(gemm_big<true>,  cudaFuncAttributeMaxDynamicSharedMemorySize, SM_BYTES);
    cudaFuncSetAttribute(gemm_small3,     cudaFuncAttributeMaxDynamicSharedMemorySize, SM_BYTES);
    cudaFuncSetAttribute(gemm_small1,     cudaFuncAttributeMaxDynamicSharedMemorySize, SM_BYTES);

    // independent small GEMMs: T = x@th0, U = xi@w0, U1 = xi@w1
    GemmJob j0 = { x,  th0, T  };
    GemmJob j1 = { xi, w0,  U  };
    GemmJob j2 = { xi, w1,  U1 };
    gemm_small3<<<dim3(64, 1, 3), 512, SM_BYTES>>>(j0, j1, j2);

    // ---- layer 0 ----
    gemm_big<false><<<dim3(32, 8), 512, SM_BYTES>>>(Hs, T, MP, 8192, 32);
    reduce_msg_k<<<2048, 256>>>(MP, ew0, M);
    gemm_big<true ><<<dim3(64, 4), 512, SM_BYTES>>>(Ht, M, ZP, 8192, 32);
    reduce_x1_k<<<4096, 256>>>(ZP, U, b0, X);

    // ---- layer 1 ----
    gemm_small1<<<64, 512, SM_BYTES>>>(X, th1, T);
    gemm_big<false><<<dim3(32, 8), 512, SM_BYTES>>>(Hs, T, MP, 8192, 32);
    reduce_msg_k<<<2048, 256>>>(MP, ew1, M);
    gemm_big<true ><<<dim3(64, 4), 512, SM_BYTES>>>(Ht, M, ZP, 8192, 32);
    reduce_x2_k<<<4096, 256>>>(ZP, U1, b1, X);

    // ---- head ----
    fc_k<<<32, 256>>>(X, st, fcw, fcb, out);
}

// round 11
// speedup vs baseline: 1.1424x; 1.1424x over previous
#include <cuda_runtime.h>
#include <cuda_bf16.h>

#define JAX_PARTITIONABLE 1

// ---------------- scratch (__device__ globals; no allocation) ----------------
__device__ float g_T[8192 * 128];          // X_in @ theta
__device__ float g_U[8192 * 128];          // xi @ w_trans0
__device__ float g_U1[8192 * 128];         // xi @ w_trans1
__device__ float g_X[8192 * 128];          // X1 then X2
__device__ float g_msg[4096 * 128];        // edge messages (ew-scaled)
__device__ float g_msgP[8 * 4096 * 128];   // split-K partials for Hs GEMM
__device__ float g_ZP[4 * 8192 * 128];     // split-K partials for Ht^T GEMM

// ------------------------------- helpers ------------------------------------
__device__ __forceinline__ unsigned rotl32(unsigned v, int s) {
    return __funnelshift_l(v, v, s);
}

// bf16 2-way split of a k-pair (f0 = even k, f1 = odd k) -> packed hi, lo u32.
__device__ __forceinline__ void split_pair(float f0, float f1,
                                           unsigned& H, unsigned& L) {
    __nv_bfloat162 h = __floats2bfloat162_rn(f0, f1);
    float r0 = f0 - __bfloat162float(h.x);
    float r1 = f1 - __bfloat162float(h.y);
    __nv_bfloat162 l = __floats2bfloat162_rn(r0, r1);
    H = *reinterpret_cast<unsigned*>(&h);
    L = *reinterpret_cast<unsigned*>(&l);
}

// m16n8k16 bf16 mma, fp32 accumulate
__device__ __forceinline__ void mma16(float c[4], const unsigned a[4], const unsigned b[2]) {
    asm("mma.sync.aligned.m16n8k16.row.col.f32.bf16.bf16.f32 "
        "{%0,%1,%2,%3},{%4,%5,%6,%7},{%8,%9},{%0,%1,%2,%3};"
        : "+f"(c[0]), "+f"(c[1]), "+f"(c[2]), "+f"(c[3])
        : "r"(a[0]), "r"(a[1]), "r"(a[2]), "r"(a[3]), "r"(b[0]), "r"(b[1]));
}

// JAX threefry2x32, key = (0, 42). Random bits for flat element j of (8192,128).
__device__ __forceinline__ unsigned jax_dropout_bits(unsigned j) {
    const unsigned k0 = 0u, k1 = 42u;
    const unsigned ks2 = k0 ^ k1 ^ 0x1BD11BDAu;
    unsigned x0, x1;
#if JAX_PARTITIONABLE
    x0 = 0u + k0;
    x1 = j + k1;
#else
    const unsigned HALF = 524288u;
    unsigned i = (j < HALF) ? j : (j - HALF);
    x0 = i + k0;
    x1 = (i + HALF) + k1;
#endif
#define TFR(r) do { x0 += x1; x1 = rotl32(x1, (r)); x1 ^= x0; } while (0)
    TFR(13); TFR(15); TFR(26); TFR(6);   x0 += k1;  x1 += ks2 + 1u;
    TFR(17); TFR(29); TFR(16); TFR(24);  x0 += ks2; x1 += k0 + 2u;
    TFR(13); TFR(15); TFR(26); TFR(6);   x0 += k0;  x1 += k1 + 3u;
    TFR(17); TFR(29); TFR(16); TFR(24);  x0 += k1;  x1 += ks2 + 4u;
    TFR(13); TFR(15); TFR(26); TFR(6);   x0 += ks2; x1 += k0 + 5u;
#undef TFR
#if JAX_PARTITIONABLE
    return x0 ^ x1;
#else
    return (j < 524288u) ? x0 : x1;
#endif
}

// ====================== 3-term bf16-split GEMM (k64/iter) ====================
// C[M,128] = op(A) @ B;  B is [K,128] row-major fp32.
//   TRANS_A=false: A [M,K] row-major (row stride lda)
//   TRANS_A=true : A [K,M] row-major (row stride lda), used as A^T
// 512 threads = 16 warps (4M x 4N), warp tile 32x32, **k64 per iteration**
// (4 k16 sub-steps, 96 mmas/warp between barriers), double-buffered smem,
// register prefetch of the next tile, 1 sync/iter.
// SMEM per buffer (u32):
//   AsH[128 rows][36]  (32 k-pairs + 4 pad)   4608
//   AsL  same                                  4608
//   BsH[32 k-pairs][136] (128 n + 8 pad)       4352
//   BsL  same                                  4352
static const int ASZ = 4608, BSZ = 4352;
static const int BUF_STRIDE = 2 * ASZ + 2 * BSZ;   // 17920 u32
static const int SM_BYTES = BUF_STRIDE * 2 * 4;    // 143360 B

template <bool TRANS_A>
__device__ __forceinline__ float4 loadA(const float* __restrict__ A, int lda,
                                        int m0, int kc, int row, int kq) {
    if (TRANS_A) {
        const float* p = A + (size_t)(kc + kq * 4) * lda + m0 + row;
        float4 v;
        v.x = p[0];
        v.y = p[(size_t)lda];
        v.z = p[2 * (size_t)lda];
        v.w = p[3 * (size_t)lda];
        return v;
    } else {
        return *(const float4*)(A + (size_t)(m0 + row) * lda + kc + kq * 4);
    }
}

__device__ __forceinline__ void stA(unsigned* __restrict__ AsH,
                                    unsigned* __restrict__ AsL,
                                    int row, int kq, float4 v) {
    unsigned h0, l0, h1, l1;
    split_pair(v.x, v.y, h0, l0);
    split_pair(v.z, v.w, h1, l1);
    *(uint2*)&AsH[row * 36 + 2 * kq] = make_uint2(h0, h1);
    *(uint2*)&AsL[row * 36 + 2 * kq] = make_uint2(l0, l1);
}

__device__ __forceinline__ void stB(unsigned* __restrict__ BsH,
                                    unsigned* __restrict__ BsL,
                                    int p, int n, float4 r0, float4 r1) {
    unsigned h[4], l[4];
    split_pair(r0.x, r1.x, h[0], l[0]);
    split_pair(r0.y, r1.y, h[1], l[1]);
    split_pair(r0.z, r1.z, h[2], l[2]);
    split_pair(r0.w, r1.w, h[3], l[3]);
    *(uint4*)&BsH[p * 136 + n] = make_uint4(h[0], h[1], h[2], h[3]);
    *(uint4*)&BsL[p * 136 + n] = make_uint4(l[0], l[1], l[2], l[3]);
}

template <bool TRANS_A>
__device__ __forceinline__ void gemm_body_bf(
    const float* __restrict__ A, const float* __restrict__ B,
    float* __restrict__ Cp, int lda, int k_iters, int mblk, int split, int gx)
{
    extern __shared__ unsigned sm[];
    const int tid = threadIdx.x;
    const int lane = tid & 31;
    const int wid = tid >> 5;              // 0..15
    const int wm = (wid & 3) * 32;
    const int wn = (wid >> 2) * 32;
    const int g = lane >> 2;               // 0..7
    const int t = lane & 3;                // 0..3
    const int m0 = mblk * 128;
    const int k00 = split * k_iters * 64;

    // staging geometry: A -> 4 tasks of one float4 (2048 tasks);
    //                   B -> 2 tasks of two float4 (1024 tasks)
    int ar_row[4], ar_kq[4];
#pragma unroll
    for (int r = 0; r < 4; ++r) {
        int task = tid + r * 512;
        if (TRANS_A) { ar_row[r] = task & 127; ar_kq[r] = task >> 7; }   // kq 0..15
        else         { ar_row[r] = task >> 4;  ar_kq[r] = task & 15; }
    }
    int b_p[2], b_n[2];
#pragma unroll
    for (int r = 0; r < 2; ++r) {
        int task = tid + r * 512;
        b_p[r] = task >> 5;                // 0..31 (k-pair)
        b_n[r] = (task & 31) * 4;          // n quad
    }

    float acc[2][4][4];
#pragma unroll
    for (int mt = 0; mt < 2; ++mt)
#pragma unroll
        for (int nt = 0; nt < 4; ++nt)
#pragma unroll
            for (int i = 0; i < 4; ++i) acc[mt][nt][i] = 0.f;

    float4 av[4], bv0[2], bv1[2];

    // prologue: load + stage tile 0 into buffer 0
    int kc = k00;
#pragma unroll
    for (int r = 0; r < 4; ++r)
        av[r] = loadA<TRANS_A>(A, lda, m0, kc, ar_row[r], ar_kq[r]);
#pragma unroll
    for (int r = 0; r < 2; ++r) {
        bv0[r] = *(const float4*)(B + (size_t)(kc + 2 * b_p[r]) * 128 + b_n[r]);
        bv1[r] = *(const float4*)(B + (size_t)(kc + 2 * b_p[r] + 1) * 128 + b_n[r]);
    }
#pragma unroll
    for (int r = 0; r < 4; ++r) stA(sm, sm + ASZ, ar_row[r], ar_kq[r], av[r]);
#pragma unroll
    for (int r = 0; r < 2; ++r)
        stB(sm + 2 * ASZ, sm + 2 * ASZ + BSZ, b_p[r], b_n[r], bv0[r], bv1[r]);
    __syncthreads();

    for (int it = 0; it < k_iters; ++it) {
        const unsigned* cur = sm + (it & 1) * BUF_STRIDE;
        const unsigned* cAH = cur;
        const unsigned* cAL = cur + ASZ;
        const unsigned* cBH = cur + 2 * ASZ;
        const unsigned* cBL = cur + 2 * ASZ + BSZ;
        const bool hn = (it + 1 < k_iters);

        if (hn) {  // next-tile global loads issued early (hidden under 96 mmas)
            kc = k00 + (it + 1) * 64;
#pragma unroll
            for (int r = 0; r < 4; ++r)
                av[r] = loadA<TRANS_A>(A, lda, m0, kc, ar_row[r], ar_kq[r]);
#pragma unroll
            for (int r = 0; r < 2; ++r) {
                bv0[r] = *(const float4*)(B + (size_t)(kc + 2 * b_p[r]) * 128 + b_n[r]);
                bv1[r] = *(const float4*)(B + (size_t)(kc + 2 * b_p[r] + 1) * 128 + b_n[r]);
            }
        }

#pragma unroll
        for (int ks = 0; ks < 4; ++ks) {          // four k16 sub-steps
            const int pb = ks * 8;                // pair base (0..24)
            unsigned aH[2][4], aL[2][4];
#pragma unroll
            for (int mt = 0; mt < 2; ++mt) {
                const int r0 = (wm + mt * 16 + g) * 36;
                const int r1 = r0 + 8 * 36;
                aH[mt][0] = cAH[r0 + pb + t];
                aH[mt][1] = cAH[r1 + pb + t];
                aH[mt][2] = cAH[r0 + pb + t + 4];
                aH[mt][3] = cAH[r1 + pb + t + 4];
                aL[mt][0] = cAL[r0 + pb + t];
                aL[mt][1] = cAL[r1 + pb + t];
                aL[mt][2] = cAL[r0 + pb + t + 4];
                aL[mt][3] = cAL[r1 + pb + t + 4];
            }
#pragma unroll
            for (int nt = 0; nt < 4; ++nt) {
                const int nb = wn + nt * 8 + g;
                const int j0 = (pb + t) * 136 + nb;
                const int j1 = (pb + t + 4) * 136 + nb;
                unsigned bH[2] = { cBH[j0], cBH[j1] };
                unsigned bL[2] = { cBL[j0], cBL[j1] };
#pragma unroll
                for (int mt = 0; mt < 2; ++mt) {
                    mma16(acc[mt][nt], aH[mt], bH);   // hi*hi
                    mma16(acc[mt][nt], aL[mt], bH);   // lo*hi
                    mma16(acc[mt][nt], aH[mt], bL);   // hi*lo
                }
            }
        }

        if (hn) {  // stage next tile into the other buffer
            unsigned* nb = sm + ((it + 1) & 1) * BUF_STRIDE;
#pragma unroll
            for (int r = 0; r < 4; ++r)
                stA(nb, nb + ASZ, ar_row[r], ar_kq[r], av[r]);
#pragma unroll
            for (int r = 0; r < 2; ++r)
                stB(nb + 2 * ASZ, nb + 2 * ASZ + BSZ, b_p[r], b_n[r], bv0[r], bv1[r]);
        }
        __syncthreads();
    }

    float* Cb = Cp + (size_t)split * gx * (128 * 128) + (size_t)m0 * 128;
#pragma unroll
    for (int mt = 0; mt < 2; ++mt)
#pragma unroll
        for (int nt = 0; nt < 4; ++nt) {
            const int r = wm + mt * 16 + g;
            const int c = wn + nt * 8 + t * 2;
            *(float2*)&Cb[(size_t)r * 128 + c] =
                make_float2(acc[mt][nt][0], acc[mt][nt][1]);
            *(float2*)&Cb[(size_t)(r + 8) * 128 + c] =
                make_float2(acc[mt][nt][2], acc[mt][nt][3]);
        }
}

// ------------------------------ GEMM kernels ---------------------------------
template <bool TRANS_A>
__global__ __launch_bounds__(512, 1)
void gemm_big(const float* __restrict__ A, const float* __restrict__ B,
              float* __restrict__ Cp, int lda, int k_iters)
{
    gemm_body_bf<TRANS_A>(A, B, Cp, lda, k_iters, blockIdx.x, blockIdx.y, gridDim.x);
}

struct GemmJob { const float* A; const float* B; float* C; };

__global__ __launch_bounds__(512, 1)
void gemm_small3(GemmJob j0, GemmJob j1, GemmJob j2)
{
    GemmJob j = (blockIdx.z == 0) ? j0 : ((blockIdx.z == 1) ? j1 : j2);
    gemm_body_bf<false>(j.A, j.B, j.C, 128, 2, blockIdx.x, 0, 64);
}

__global__ __launch_bounds__(512, 1)
void gemm_small1(const float* __restrict__ A, const float* __restrict__ B,
                 float* __restrict__ C)
{
    gemm_body_bf<false>(A, B, C, 128, 2, blockIdx.x, 0, 64);
}

// ------------------------ reduce / epilogue kernels --------------------------
__global__ void reduce_msg_k(const float* __restrict__ P, const float* __restrict__ ew,
                             float* __restrict__ out)
{
    const int i = blockIdx.x * 256 + threadIdx.x;
    float s = 0.f;
#pragma unroll
    for (int j = 0; j < 8; ++j) s += P[(size_t)j * (4096 * 128) + i];
    out[i] = s * ew[i >> 7];
}

__global__ void reduce_x1_k(const float* __restrict__ P, const float* __restrict__ U,
                            const float* __restrict__ bias, float* __restrict__ X1)
{
    const int i = blockIdx.x * 256 + threadIdx.x;
    float s = U[i] + bias[i & 127];
#pragma unroll
    for (int j = 0; j < 4; ++j) s += P[(size_t)j * (8192 * 128) + i];
    s = (s >= 0.f) ? s : 0.01f * s;
    const unsigned bits = jax_dropout_bits((unsigned)i);
    X1[i] = (bits & 0x80000000u) ? 0.f : (s + s);
}

__global__ void reduce_x2_k(const float* __restrict__ P, const float* __restrict__ U,
                            const float* __restrict__ bias, float* __restrict__ X2)
{
    const int i = blockIdx.x * 256 + threadIdx.x;
    float s = U[i] + bias[i & 127];
#pragma unroll
    for (int j = 0; j < 4; ++j) s += P[(size_t)j * (8192 * 128) + i];
    s = (s >= 0.f) ? s : 0.01f * s;
    s = (s >= 0.f) ? s : 0.01f * s;
    X2[i] = s;
}

__global__ void fc_k(const float* __restrict__ X, const float* __restrict__ state,
                     const float* __restrict__ fcw, const float* __restrict__ fcb,
                     float* __restrict__ out)
{
    const int n = blockIdx.x * 256 + threadIdx.x;
    const float4* xr = (const float4*)(X + (size_t)n * 128);
    const float4* w4 = (const float4*)fcw;
    float s = 0.f;
#pragma unroll
    for (int i = 0; i < 32; ++i) {
        float4 a = xr[i], b = w4[i];
        s += a.x * b.x + a.y * b.y + a.z * b.z + a.w * b.w;
    }
    out[n] = s + state[n] * fcw[128] + fcb[0];
}

// --------------------------------- launch ------------------------------------
extern "C" void kernel_launch(void* const* d_in, const int* in_sizes, int n_in,
                              void* d_out, int out_size)
{
    const float* xi   = (const float*)d_in[0];
    const float* x    = (const float*)d_in[1];
    const float* Ht   = (const float*)d_in[2];
    const float* Hs   = (const float*)d_in[3];
    const float* st   = (const float*)d_in[4];
    const float* w0   = (const float*)d_in[5];
    const float* th0  = (const float*)d_in[6];
    const float* ew0  = (const float*)d_in[7];
    const float* b0   = (const float*)d_in[8];
    const float* w1   = (const float*)d_in[9];
    const float* th1  = (const float*)d_in[10];
    const float* ew1  = (const float*)d_in[11];
    const float* b1   = (const float*)d_in[12];
    const float* fcw  = (const float*)d_in[13];
    const float* fcb  = (const float*)d_in[14];
    float* out = (float*)d_out;

    float *T, *U, *U1, *X, *M, *MP, *ZP;
    cudaGetSymbolAddress((void**)&T,  g_T);
    cudaGetSymbolAddress((void**)&U,  g_U);
    cudaGetSymbolAddress((void**)&U1, g_U1);
    cudaGetSymbolAddress((void**)&X,  g_X);
    cudaGetSymbolAddress((void**)&M,  g_msg);
    cudaGetSymbolAddress((void**)&MP, g_msgP);
    cudaGetSymbolAddress((void**)&ZP, g_ZP);

    cudaFuncSetAttribute(gemm_big<false>, cudaFuncAttributeMaxDynamicSharedMemorySize, SM_BYTES);
    cudaFuncSetAttribute(gemm_big<true>,  cudaFuncAttributeMaxDynamicSharedMemorySize, SM_BYTES);
    cudaFuncSetAttribute(gemm_small3,     cudaFuncAttributeMaxDynamicSharedMemorySize, SM_BYTES);
    cudaFuncSetAttribute(gemm_small1,     cudaFuncAttributeMaxDynamicSharedMemorySize, SM_BYTES);

    // independent small GEMMs: T = x@th0, U = xi@w0, U1 = xi@w1
    GemmJob j0 = { x,  th0, T  };
    GemmJob j1 = { xi, w0,  U  };
    GemmJob j2 = { xi, w1,  U1 };
    gemm_small3<<<dim3(64, 1, 3), 512, SM_BYTES>>>(j0, j1, j2);

    // ---- layer 0 ----
    gemm_big<false><<<dim3(32, 8), 512, SM_BYTES>>>(Hs, T, MP, 8192, 16);
    reduce_msg_k<<<2048, 256>>>(MP, ew0, M);
    gemm_big<true ><<<dim3(64, 4), 512, SM_BYTES>>>(Ht, M, ZP, 8192, 16);
    reduce_x1_k<<<4096, 256>>>(ZP, U, b0, X);

    // ---- layer 1 ----
    gemm_small1<<<64, 512, SM_BYTES>>>(X, th1, T);
    gemm_big<false><<<dim3(32, 8), 512, SM_BYTES>>>(Hs, T, MP, 8192, 16);
    reduce_msg_k<<<2048, 256>>>(MP, ew1, M);
    gemm_big<true ><<<dim3(64, 4), 512, SM_BYTES>>>(Ht, M, ZP, 8192, 16);
    reduce_x2_k<<<4096, 256>>>(ZP, U1, b1, X);

    // ---- head ----
    fc_k<<<32, 256>>>(X, st, fcw, fcb, out);
}